// round 3
// baseline (speedup 1.0000x reference)
#include <cuda_runtime.h>
#include <cuda_bf16.h>

// Problem constants (fixed by setup_inputs): d=64, nq=1024, nk=2048, batch=1
#define D   64
#define NQ  1024
#define NK  2048

// Scratch: projected (and bias-folded) q/k features
__device__ float g_qpb[NQ * D];   // qp[q][h] + b1[h]
__device__ float g_kpb[NK * D];   // kp[k][h]

// ---------------------------------------------------------------------------
// K1: qpb[q][h] = b1[h] + sum_d W1[h][d]     * query[d][q]
//     kpb[k][h] =         sum_d W1[h][64+d]  * key[d][k]
// One block = 4 rows; 256 threads = 64 h x 4 rows.
// ---------------------------------------------------------------------------
__global__ __launch_bounds__(256)
void k1_project(const float* __restrict__ query,
                const float* __restrict__ key,
                const float* __restrict__ W1,
                const float* __restrict__ b1)
{
    __shared__ float w1_s[64 * 129];  // pad 128->129 to avoid 32-way conflicts

    int tid = threadIdx.x;
    for (int i = tid; i < 64 * 128; i += 256) {
        int h = i >> 7, d2 = i & 127;
        w1_s[h * 129 + d2] = W1[i];
    }
    __syncthreads();

    int h = tid & 63;
    int r = tid >> 6;                 // 0..3
    int row = blockIdx.x * 4 + r;     // 0..3071

    if (row < NQ) {
        const float* src = query + row;       // query[d*NQ + row]
        float acc = b1[h];
        #pragma unroll
        for (int d = 0; d < 64; d++)
            acc += w1_s[h * 129 + d] * src[d * NQ];
        g_qpb[row * D + h] = acc;
    } else {
        int k = row - NQ;
        const float* src = key + k;           // key[d*NK + k]
        float acc = 0.0f;
        #pragma unroll
        for (int d = 0; d < 64; d++)
            acc += w1_s[h * 129 + 64 + d] * src[d * NK];
        g_kpb[k * D + h] = acc;
    }
}

// ---------------------------------------------------------------------------
// K2: scores[q][k] = b2 + sum_h W2[h] * relu(qpb[q][h] + kpb[k][h])
// Tile: 16 q x 64 k per block, 256 threads, 4 scores per thread.
// ---------------------------------------------------------------------------
__global__ __launch_bounds__(256)
void k2_scores(const float* __restrict__ W2,
               const float* __restrict__ b2,
               float* __restrict__ scores)
{
    __shared__ float q_s[16 * 68];    // stride 68: kills stride-64 bank conflict
    __shared__ float k_s[64 * 68];
    __shared__ float w2_s[64];

    int tid   = threadIdx.x;
    int qbase = blockIdx.y * 16;
    int kbase = blockIdx.x * 64;

    for (int i = tid; i < 16 * 64; i += 256) {
        int r = i >> 6, h = i & 63;
        q_s[r * 68 + h] = g_qpb[(qbase + r) * D + h];
    }
    for (int i = tid; i < 64 * 64; i += 256) {
        int r = i >> 6, h = i & 63;
        k_s[r * 68 + h] = g_kpb[(kbase + r) * D + h];
    }
    if (tid < 64) w2_s[tid] = W2[tid];
    __syncthreads();

    int qi = tid >> 4;            // 0..15
    int kg = (tid & 15) << 2;     // 0,4,...,60  -> this thread's 4 k's

    float bias = b2[0];
    float a0 = bias, a1 = bias, a2 = bias, a3 = bias;

    #pragma unroll
    for (int h = 0; h < 64; h += 4) {
        float4 qv = *(const float4*)&q_s[qi * 68 + h];
        float4 wv = *(const float4*)&w2_s[h];
        float4 k0 = *(const float4*)&k_s[(kg + 0) * 68 + h];
        float4 k1 = *(const float4*)&k_s[(kg + 1) * 68 + h];
        float4 k2 = *(const float4*)&k_s[(kg + 2) * 68 + h];
        float4 k3 = *(const float4*)&k_s[(kg + 3) * 68 + h];

        a0 += wv.x * fmaxf(qv.x + k0.x, 0.0f);
        a0 += wv.y * fmaxf(qv.y + k0.y, 0.0f);
        a0 += wv.z * fmaxf(qv.z + k0.z, 0.0f);
        a0 += wv.w * fmaxf(qv.w + k0.w, 0.0f);

        a1 += wv.x * fmaxf(qv.x + k1.x, 0.0f);
        a1 += wv.y * fmaxf(qv.y + k1.y, 0.0f);
        a1 += wv.z * fmaxf(qv.z + k1.z, 0.0f);
        a1 += wv.w * fmaxf(qv.w + k1.w, 0.0f);

        a2 += wv.x * fmaxf(qv.x + k2.x, 0.0f);
        a2 += wv.y * fmaxf(qv.y + k2.y, 0.0f);
        a2 += wv.z * fmaxf(qv.z + k2.z, 0.0f);
        a2 += wv.w * fmaxf(qv.w + k2.w, 0.0f);

        a3 += wv.x * fmaxf(qv.x + k3.x, 0.0f);
        a3 += wv.y * fmaxf(qv.y + k3.y, 0.0f);
        a3 += wv.z * fmaxf(qv.z + k3.z, 0.0f);
        a3 += wv.w * fmaxf(qv.w + k3.w, 0.0f);
    }

    float4* dst = (float4*)&scores[(qbase + qi) * NK + kbase + kg];
    *dst = make_float4(a0, a1, a2, a3);
}

// ---------------------------------------------------------------------------
// K3: softmax over k + out[d][q] = sum_m prob[q][m] * value[d][m]
// Block = 8 q rows, 256 threads. Warp-per-row softmax stats (scores re-read
// from L2), then chunked PV with prob/value tiles in smem.
// ---------------------------------------------------------------------------
__global__ __launch_bounds__(256)
void k3_softmax_pv(const float* __restrict__ scores,
                   const float* __restrict__ value,
                   float* __restrict__ out)
{
    __shared__ float rowmax[8], rowinv[8];
    __shared__ float p_s[8 * 132];    // prob chunk, pad 128->132 (16B aligned)
    __shared__ float v_s[64 * 132];   // value chunk

    int tid   = threadIdx.x;
    int qbase = blockIdx.x * 8;
    int w     = tid >> 5;      // warp id = row within tile
    int lane  = tid & 31;

    // --- softmax stats: one warp per q row ---
    {
        const float* srow = scores + (qbase + w) * NK;
        float lm = -1e30f;
        for (int i = lane; i < NK; i += 32)
            lm = fmaxf(lm, srow[i]);
        #pragma unroll
        for (int o = 16; o > 0; o >>= 1)
            lm = fmaxf(lm, __shfl_xor_sync(0xffffffffu, lm, o));

        float ls = 0.0f;
        for (int i = lane; i < NK; i += 32)
            ls += __expf(srow[i] - lm);
        #pragma unroll
        for (int o = 16; o > 0; o >>= 1)
            ls += __shfl_xor_sync(0xffffffffu, ls, o);

        if (lane == 0) {
            rowmax[w] = lm;
            rowinv[w] = 1.0f / ls;
        }
    }
    __syncthreads();

    // --- PV over 128-wide m chunks ---
    int q = tid & 7;           // 0..7
    int d = tid >> 3;          // 0..31 (second output at d+32)
    float acc0 = 0.0f, acc1 = 0.0f;

    for (int c = 0; c < NK; c += 128) {
        __syncthreads();
        // prob chunk: 8 x 128
        for (int i = tid; i < 8 * 128; i += 256) {
            int qq = i >> 7, mm = i & 127;
            float s = scores[(qbase + qq) * NK + c + mm];
            p_s[qq * 132 + mm] = __expf(s - rowmax[qq]) * rowinv[qq];
        }
        // value chunk: 64 x 128 (float4 coalesced)
        for (int i = tid; i < 2048; i += 256) {
            int dd = i >> 5, m4 = (i & 31) << 2;
            *(float4*)&v_s[dd * 132 + m4] =
                *(const float4*)&value[dd * NK + c + m4];
        }
        __syncthreads();

        #pragma unroll
        for (int mm = 0; mm < 128; mm += 4) {
            float4 p4 = *(const float4*)&p_s[q * 132 + mm];
            float4 v0 = *(const float4*)&v_s[d * 132 + mm];
            float4 v1 = *(const float4*)&v_s[(d + 32) * 132 + mm];
            acc0 += p4.x * v0.x + p4.y * v0.y + p4.z * v0.z + p4.w * v0.w;
            acc1 += p4.x * v1.x + p4.y * v1.y + p4.z * v1.z + p4.w * v1.w;
        }
    }

    out[d * NQ + qbase + q]        = acc0;
    out[(d + 32) * NQ + qbase + q] = acc1;
}

// ---------------------------------------------------------------------------
// Launch: out = d_out[0 : 64*1024], scores = d_out[64*1024 : +1024*2048]
// ---------------------------------------------------------------------------
extern "C" void kernel_launch(void* const* d_in, const int* in_sizes, int n_in,
                              void* d_out, int out_size)
{
    const float* query = (const float*)d_in[0];
    const float* key   = (const float*)d_in[1];
    const float* value = (const float*)d_in[2];
    const float* W1    = (const float*)d_in[3];
    const float* b1    = (const float*)d_in[4];
    const float* W2    = (const float*)d_in[5];
    const float* b2    = (const float*)d_in[6];

    float* out    = (float*)d_out;
    float* scores = out + D * NQ;

    k1_project<<<(NQ + NK) / 4, 256>>>(query, key, W1, b1);
    k2_scores<<<dim3(NK / 64, NQ / 16), 256>>>(W2, b2, scores);
    k3_softmax_pv<<<NQ / 8, 256>>>(scores, value, out);
}

// round 4
// speedup vs baseline: 1.2485x; 1.2485x over previous
#include <cuda_runtime.h>
#include <cuda_bf16.h>

// Problem constants (fixed by setup_inputs): d=64, nq=1024, nk=2048, batch=1
#define D   64
#define NQ  1024
#define NK  2048

// Scratch: projected features stored TRANSPOSED (h-major) so k2 can tile
// shared memory without a transpose (conflict-free loads).
__device__ float g_qpbT[D * NQ];   // qpbT[h][q] = b1[h] + sum_d W1q[h][d] query[d][q]
__device__ float g_kpbT[D * NK];   // kpbT[h][k] =         sum_d W1k[h][d] key[d][k]

// ---------------------------------------------------------------------------
// K1: projection GEMMs, coalesced. Block = 32 columns (of query or key),
// 256 threads = 32 cols x 8 h-groups (8 h each). Lanes are contiguous
// columns -> 128B coalesced loads; weights transposed into smem [d][h].
// Grid: (NQ + NK)/32 = 96 blocks.
// ---------------------------------------------------------------------------
__global__ __launch_bounds__(256)
void k1_project(const float* __restrict__ query,
                const float* __restrict__ key,
                const float* __restrict__ W1,
                const float* __restrict__ b1)
{
    __shared__ float w_s[64 * 68];   // [d][h], stride 68 (16B-aligned rows)

    int tid     = threadIdx.x;
    int colbase = blockIdx.x * 32;
    bool isQ    = (colbase < NQ);
    int off     = isQ ? 0 : 64;      // W1 column offset: W1q vs W1k

    // Load 64x64 weight half, transposed: read coalesced, write strided.
    for (int i = tid; i < 64 * 64; i += 256) {
        int d = i & 63, h = i >> 6;
        w_s[d * 68 + h] = W1[h * 128 + off + d];
    }
    __syncthreads();

    int lane = tid & 31;
    int h0   = (tid >> 5) * 8;       // 8 h's per thread

    const float* src;
    int stride, col;
    if (isQ) { col = colbase + lane;      src = query + col; stride = NQ; }
    else     { col = colbase - NQ + lane; src = key   + col; stride = NK; }

    float acc[8];
    #pragma unroll
    for (int j = 0; j < 8; j++) acc[j] = isQ ? b1[h0 + j] : 0.0f;

    #pragma unroll 8
    for (int d = 0; d < 64; d++) {
        float x = src[d * stride];
        float4 w0 = *(const float4*)&w_s[d * 68 + h0];
        float4 w1 = *(const float4*)&w_s[d * 68 + h0 + 4];
        acc[0] += w0.x * x;  acc[1] += w0.y * x;
        acc[2] += w0.z * x;  acc[3] += w0.w * x;
        acc[4] += w1.x * x;  acc[5] += w1.y * x;
        acc[6] += w1.z * x;  acc[7] += w1.w * x;
    }

    float* dst = isQ ? g_qpbT : g_kpbT;
    #pragma unroll
    for (int j = 0; j < 8; j++)
        dst[(h0 + j) * stride + col] = acc[j];
}

// ---------------------------------------------------------------------------
// K2: scores[q][k] = b2 + sum_h W2[h] * relu(qpb[q][h] + kpb[k][h])
// Tile: 64q x 64k per block, 256 threads, 4x4 register tile per thread.
// smem tiles are [h][row] (straight copy from transposed gmem scratch):
// per-h loads are 2 float4s whose 8-lane phases span 32 distinct banks.
// Grid: (NK/64, NQ/64) = (32, 16) = 512 blocks.
// ---------------------------------------------------------------------------
__global__ __launch_bounds__(256)
void k2_scores(const float* __restrict__ W2,
               const float* __restrict__ b2,
               float* __restrict__ scores)
{
    __shared__ float qs[64 * 68];    // [h][qi]
    __shared__ float ks[64 * 68];    // [h][ki]
    __shared__ float w2_s[64];

    int tid   = threadIdx.x;
    int qbase = blockIdx.y * 64;
    int kbase = blockIdx.x * 64;

    // Straight (no-transpose) tile copies, float4, conflict-free.
    #pragma unroll
    for (int it = 0; it < 4; it++) {
        int i  = tid + it * 256;           // 0..1023 over 64h x 16 float4
        int h  = i >> 4;
        int r4 = (i & 15) << 2;
        *(float4*)&qs[h * 68 + r4] = *(const float4*)&g_qpbT[h * NQ + qbase + r4];
        *(float4*)&ks[h * 68 + r4] = *(const float4*)&g_kpbT[h * NK + kbase + r4];
    }
    if (tid < 64) w2_s[tid] = W2[tid];
    __syncthreads();

    int qg = tid >> 4;        // 0..15 -> 4 q rows
    int kg = tid & 15;        // 0..15 -> 4 k cols

    float acc[4][4];
    float bias = b2[0];
    #pragma unroll
    for (int i = 0; i < 4; i++)
        #pragma unroll
        for (int j = 0; j < 4; j++) acc[i][j] = 0.0f;

    #pragma unroll 8
    for (int h = 0; h < 64; h++) {
        float4 q4 = *(const float4*)&qs[h * 68 + (qg << 2)];
        float4 k4 = *(const float4*)&ks[h * 68 + (kg << 2)];
        float  w  = w2_s[h];
        float qa[4] = {q4.x, q4.y, q4.z, q4.w};
        float ka[4] = {k4.x, k4.y, k4.z, k4.w};
        #pragma unroll
        for (int i = 0; i < 4; i++)
            #pragma unroll
            for (int j = 0; j < 4; j++)
                acc[i][j] = fmaf(w, fmaxf(qa[i] + ka[j], 0.0f), acc[i][j]);
    }

    #pragma unroll
    for (int i = 0; i < 4; i++) {
        float4 v = make_float4(acc[i][0] + bias, acc[i][1] + bias,
                               acc[i][2] + bias, acc[i][3] + bias);
        *(float4*)&scores[(qbase + qg * 4 + i) * NK + kbase + (kg << 2)] = v;
    }
}

// ---------------------------------------------------------------------------
// K3: softmax over k + out[d][q] = sum_m prob[q][m] * value[d][m]
// Block = 8 q rows, 256 threads (one wave: 128 blocks).
// Per-thread tile: 4 d x 1 q, with the m-dimension split across 2 thread
// groups (cross-reduced in smem at the end).
// ---------------------------------------------------------------------------
__global__ __launch_bounds__(256)
void k3_softmax_pv(const float* __restrict__ scores,
                   const float* __restrict__ value,
                   float* __restrict__ out)
{
    __shared__ float rowmax[8], rowinv[8];
    __shared__ float p_s[8 * 132];    // prob chunk (pad keeps 16B align, no conflicts)
    __shared__ float v_s[64 * 132];   // value chunk (also reused as reduce buffer)

    int tid   = threadIdx.x;
    int qbase = blockIdx.x * 8;
    int w     = tid >> 5;      // warp id = q row within tile
    int lane  = tid & 31;

    // --- softmax stats: one warp per q row ---
    {
        const float* srow = scores + (qbase + w) * NK;
        float lm = -1e30f;
        for (int i = lane; i < NK; i += 32)
            lm = fmaxf(lm, srow[i]);
        #pragma unroll
        for (int o = 16; o > 0; o >>= 1)
            lm = fmaxf(lm, __shfl_xor_sync(0xffffffffu, lm, o));

        float ls = 0.0f;
        for (int i = lane; i < NK; i += 32)
            ls += __expf(srow[i] - lm);
        #pragma unroll
        for (int o = 16; o > 0; o >>= 1)
            ls += __shfl_xor_sync(0xffffffffu, ls, o);

        if (lane == 0) {
            rowmax[w] = lm;
            rowinv[w] = 1.0f / ls;
        }
    }
    __syncthreads();

    // --- PV over 128-wide m chunks ---
    int q  = tid & 7;             // 0..7
    int dg = (tid >> 3) & 15;     // 0..15 -> 4 d rows (dg*4..dg*4+3)
    int mh = tid >> 7;            // 0/1   -> m half within chunk
    int mb = mh * 64;

    float acc[4] = {0.0f, 0.0f, 0.0f, 0.0f};

    for (int c = 0; c < NK; c += 128) {
        __syncthreads();
        // prob chunk: 8 x 128
        for (int i = tid; i < 8 * 128; i += 256) {
            int qq = i >> 7, mm = i & 127;
            float s = scores[(qbase + qq) * NK + c + mm];
            p_s[qq * 132 + mm] = __expf(s - rowmax[qq]) * rowinv[qq];
        }
        // value chunk: 64 x 128 (float4 coalesced)
        for (int i = tid; i < 2048; i += 256) {
            int dd = i >> 5, m4 = (i & 31) << 2;
            *(float4*)&v_s[dd * 132 + m4] =
                *(const float4*)&value[dd * NK + c + m4];
        }
        __syncthreads();

        #pragma unroll
        for (int mm = 0; mm < 64; mm += 4) {
            float4 p4 = *(const float4*)&p_s[q * 132 + mb + mm];
            #pragma unroll
            for (int j = 0; j < 4; j++) {
                float4 v4 = *(const float4*)&v_s[(dg * 4 + j) * 132 + mb + mm];
                acc[j] += p4.x * v4.x + p4.y * v4.y + p4.z * v4.z + p4.w * v4.w;
            }
        }
    }

    // --- cross m-half reduction via smem (reuse v_s) ---
    __syncthreads();
    if (mh == 1)
        *(float4*)&v_s[(tid - 128) * 4] = make_float4(acc[0], acc[1], acc[2], acc[3]);
    __syncthreads();
    if (mh == 0) {
        float4 other = *(const float4*)&v_s[tid * 4];
        acc[0] += other.x; acc[1] += other.y;
        acc[2] += other.z; acc[3] += other.w;
        #pragma unroll
        for (int j = 0; j < 4; j++)
            out[(dg * 4 + j) * NQ + qbase + q] = acc[j];
    }
}

// ---------------------------------------------------------------------------
// Launch: out = d_out[0 : 64*1024], scores = d_out[64*1024 : +1024*2048]
// ---------------------------------------------------------------------------
extern "C" void kernel_launch(void* const* d_in, const int* in_sizes, int n_in,
                              void* d_out, int out_size)
{
    const float* query = (const float*)d_in[0];
    const float* key   = (const float*)d_in[1];
    const float* value = (const float*)d_in[2];
    const float* W1    = (const float*)d_in[3];
    const float* b1    = (const float*)d_in[4];
    const float* W2    = (const float*)d_in[5];
    const float* b2    = (const float*)d_in[6];

    float* out    = (float*)d_out;
    float* scores = out + D * NQ;

    k1_project<<<(NQ + NK) / 32, 256>>>(query, key, W1, b1);
    k2_scores<<<dim3(NK / 64, NQ / 64), 256>>>(W2, b2, scores);
    k3_softmax_pv<<<NQ / 8, 256>>>(scores, value, out);
}

// round 5
// speedup vs baseline: 2.5918x; 2.0760x over previous
#include <cuda_runtime.h>
#include <cuda_bf16.h>

// Problem constants (fixed by setup_inputs): d=64, nq=1024, nk=2048, batch=1
#define D   64
#define NQ  1024
#define NK  2048

typedef unsigned long long ull;

// Scratch: projected features stored TRANSPOSED (h-major)
__device__ float g_qpbT[D * NQ];   // qpbT[h][q] = b1[h] + sum_d W1q[h][d] query[d][q]
__device__ float g_kpbT[D * NK];   // kpbT[h][k] =         sum_d W1k[h][d] key[d][k]

// ---- packed f32x2 helpers -------------------------------------------------
__device__ __forceinline__ void fma2(ull& acc, ull a, ull b) {
    asm("fma.rn.f32x2 %0, %1, %2, %0;" : "+l"(acc) : "l"(a), "l"(b));
}
// acc += w2 * relu(q2 + k2), all packed f32x2
__device__ __forceinline__ void relu_wfma2(ull& acc, ull q2, ull k2, ull w2) {
    asm("{\n\t"
        ".reg .b64 t;\n\t"
        ".reg .f32 lo, hi;\n\t"
        "add.rn.f32x2 t, %1, %2;\n\t"
        "mov.b64 {lo, hi}, t;\n\t"
        "max.f32 lo, lo, 0f00000000;\n\t"
        "max.f32 hi, hi, 0f00000000;\n\t"
        "mov.b64 t, {lo, hi};\n\t"
        "fma.rn.f32x2 %0, %3, t, %0;\n\t"
        "}" : "+l"(acc) : "l"(q2), "l"(k2), "l"(w2));
}
__device__ __forceinline__ float2 upk(ull v) {
    float2 f;
    asm("mov.b64 {%0, %1}, %2;" : "=f"(f.x), "=f"(f.y) : "l"(v));
    return f;
}

// ---------------------------------------------------------------------------
// K1: projection GEMMs, smem-staged. Block = 32 cols x 32 h (h-split x2).
// Grid (96, 2). 256 threads = 32 cols x 8 warps x 4 h each.
// ---------------------------------------------------------------------------
__global__ __launch_bounds__(256)
void k1_project(const float* __restrict__ query,
                const float* __restrict__ key,
                const float* __restrict__ W1,
                const float* __restrict__ b1)
{
    __shared__ float in_s[64 * 32];   // [d][c]
    __shared__ float w_s[64 * 36];    // [d][hl], pad 36

    int tid     = threadIdx.x;
    int colbase = blockIdx.x * 32;
    int hbase   = blockIdx.y * 32;
    bool isQ    = (colbase < NQ);
    int off     = isQ ? 0 : 64;
    int stride  = isQ ? NQ : NK;
    int cb      = isQ ? colbase : colbase - NQ;
    const float* src = isQ ? query : key;

    // input tile: 64 d x 32 cols, coalesced, MLP=8
    #pragma unroll
    for (int it = 0; it < 8; it++) {
        int i = tid + it * 256;                 // d = i>>5, c = i&31
        in_s[i] = src[(i >> 5) * stride + cb + (i & 31)];
    }
    // weight tile: 32 h x 64 d, transposed into [d][hl]
    #pragma unroll
    for (int it = 0; it < 8; it++) {
        int i = tid + it * 256;
        int d = i & 63, hl = i >> 6;
        w_s[d * 36 + hl] = W1[(hbase + hl) * 128 + off + d];
    }
    __syncthreads();

    int lane = tid & 31;
    int wrp  = tid >> 5;
    int hl0  = wrp * 4;

    float acc[4];
    #pragma unroll
    for (int j = 0; j < 4; j++)
        acc[j] = isQ ? b1[hbase + hl0 + j] : 0.0f;

    #pragma unroll 8
    for (int d = 0; d < 64; d++) {
        float  x  = in_s[d * 32 + lane];
        float4 w4 = *(const float4*)&w_s[d * 36 + hl0];
        acc[0] = fmaf(w4.x, x, acc[0]);
        acc[1] = fmaf(w4.y, x, acc[1]);
        acc[2] = fmaf(w4.z, x, acc[2]);
        acc[3] = fmaf(w4.w, x, acc[3]);
    }

    float* dst = isQ ? g_qpbT : g_kpbT;
    #pragma unroll
    for (int j = 0; j < 4; j++)
        dst[(hbase + hl0 + j) * stride + cb + lane] = acc[j];
}

// ---------------------------------------------------------------------------
// K2: scores[q][k] = b2 + sum_h W2[h] * relu(qpb[q][h] + kpb[k][h])
// Tile 64q x 128k per block, 256 threads, per-thread 4q x 8k, packed f32x2.
// q tile stored DUPLICATED in smem so packed q operands load directly.
// Grid (NK/128, NQ/64) = (16, 16).
// ---------------------------------------------------------------------------
__global__ __launch_bounds__(256)
void k2_scores(const float* __restrict__ W2,
               const float* __restrict__ b2,
               float* __restrict__ scores)
{
    __shared__ float qs2[64 * 132];   // [h][2*64]  duplicated q values
    __shared__ float ks [64 * 132];   // [h][128]
    __shared__ float w2d[128];        // duplicated W2

    int tid   = threadIdx.x;
    int qbase = blockIdx.y * 64;
    int kbase = blockIdx.x * 128;

    #pragma unroll
    for (int it = 0; it < 16; it++) {
        int i = tid + it * 256;               // 64h x 64r
        int h = i >> 6, r = i & 63;
        float v = g_qpbT[h * NQ + qbase + r];
        *(float2*)&qs2[h * 132 + 2 * r] = make_float2(v, v);
    }
    #pragma unroll
    for (int it = 0; it < 8; it++) {
        int i = tid + it * 256;               // 64h x 32 float4
        int h = i >> 5, c4 = (i & 31) << 2;
        *(float4*)&ks[h * 132 + c4] = *(const float4*)&g_kpbT[h * NK + kbase + c4];
    }
    if (tid < 64) {
        float w = W2[tid];
        *(float2*)&w2d[2 * tid] = make_float2(w, w);
    }
    __syncthreads();

    int qg = tid >> 4;        // 0..15 -> q rows 4qg..4qg+3
    int kg = tid & 15;        // 0..15 -> k cols {4kg..4kg+3} u {64+4kg..}

    ull acc[4][4];
    #pragma unroll
    for (int i = 0; i < 4; i++)
        #pragma unroll
        for (int j = 0; j < 4; j++) acc[i][j] = 0ull;

    #pragma unroll 4
    for (int h = 0; h < 64; h++) {
        ull w2v = *(const ull*)&w2d[2 * h];
        const float* qrow = &qs2[h * 132 + 8 * qg];
        ulonglong2 qA = *(const ulonglong2*)qrow;         // (q0,q0),(q1,q1)
        ulonglong2 qB = *(const ulonglong2*)(qrow + 4);   // (q2,q2),(q3,q3)
        ulonglong2 kA = *(const ulonglong2*)&ks[h * 132 + 4 * kg];
        ulonglong2 kB = *(const ulonglong2*)&ks[h * 132 + 64 + 4 * kg];
        ull qd[4] = {qA.x, qA.y, qB.x, qB.y};
        ull kp[4] = {kA.x, kA.y, kB.x, kB.y};
        #pragma unroll
        for (int i = 0; i < 4; i++)
            #pragma unroll
            for (int j = 0; j < 4; j++)
                relu_wfma2(acc[i][j], qd[i], kp[j], w2v);
    }

    float bias = b2[0];
    #pragma unroll
    for (int i = 0; i < 4; i++) {
        float* row = &scores[(qbase + 4 * qg + i) * NK + kbase];
        float2 a0 = upk(acc[i][0]), a1 = upk(acc[i][1]);
        float2 a2 = upk(acc[i][2]), a3 = upk(acc[i][3]);
        *(float4*)&row[4 * kg] =
            make_float4(a0.x + bias, a0.y + bias, a1.x + bias, a1.y + bias);
        *(float4*)&row[64 + 4 * kg] =
            make_float4(a2.x + bias, a2.y + bias, a3.x + bias, a3.y + bias);
    }
}

// ---------------------------------------------------------------------------
// K3: softmax over k + out[d][q] = sum_m prob[q][m] * value[d][m]
// Block = 8 q rows, 256 threads, grid 128. Stats with 4-way MLP; PV with
// register-prefetch software pipeline + packed fma.f32x2.
// ---------------------------------------------------------------------------
__device__ __forceinline__ void k3_load_chunk(const float* __restrict__ scores,
                                              const float* __restrict__ value,
                                              int qbase, int c, int tid,
                                              float4* vr, float* sr)
{
    #pragma unroll
    for (int it = 0; it < 4; it++) {
        int i = tid + it * 256;
        sr[it] = scores[(qbase + (i >> 7)) * NK + c + (i & 127)];
    }
    #pragma unroll
    for (int it = 0; it < 8; it++) {
        int i = tid + it * 256;
        vr[it] = *(const float4*)&value[(i >> 5) * NK + c + ((i & 31) << 2)];
    }
}

__global__ __launch_bounds__(256)
void k3_softmax_pv(const float* __restrict__ scores,
                   const float* __restrict__ value,
                   float* __restrict__ out)
{
    __shared__ float rowmax[8], rowinv[8];
    __shared__ float p_s[8 * 132];
    __shared__ float v_s[64 * 132];

    int tid   = threadIdx.x;
    int qbase = blockIdx.x * 8;
    int w     = tid >> 5;
    int lane  = tid & 31;

    // --- softmax stats: one warp per q row, 4 independent partials ---
    {
        const float* srow = scores + (qbase + w) * NK;
        float a = -1e30f, b = -1e30f, cc = -1e30f, d = -1e30f;
        #pragma unroll
        for (int i = 0; i < NK; i += 128) {
            a  = fmaxf(a,  srow[i + lane]);
            b  = fmaxf(b,  srow[i + lane + 32]);
            cc = fmaxf(cc, srow[i + lane + 64]);
            d  = fmaxf(d,  srow[i + lane + 96]);
        }
        float lm = fmaxf(fmaxf(a, b), fmaxf(cc, d));
        #pragma unroll
        for (int o = 16; o > 0; o >>= 1)
            lm = fmaxf(lm, __shfl_xor_sync(0xffffffffu, lm, o));

        float sa = 0.0f, sb = 0.0f, sc = 0.0f, sd = 0.0f;
        #pragma unroll
        for (int i = 0; i < NK; i += 128) {
            sa += __expf(srow[i + lane]      - lm);
            sb += __expf(srow[i + lane + 32] - lm);
            sc += __expf(srow[i + lane + 64] - lm);
            sd += __expf(srow[i + lane + 96] - lm);
        }
        float ls = (sa + sb) + (sc + sd);
        #pragma unroll
        for (int o = 16; o > 0; o >>= 1)
            ls += __shfl_xor_sync(0xffffffffu, ls, o);

        if (lane == 0) { rowmax[w] = lm; rowinv[w] = 1.0f / ls; }
    }

    // --- PV, software-pipelined ---
    int q  = tid & 7;
    int dg = (tid >> 3) & 15;
    int mh = tid >> 7;
    int mb = mh * 64;

    ull acc2[4] = {0ull, 0ull, 0ull, 0ull};

    float4 vr[8]; float sr[4];
    k3_load_chunk(scores, value, qbase, 0, tid, vr, sr);

    for (int c = 0; c < NK; c += 128) {
        __syncthreads();
        #pragma unroll
        for (int it = 0; it < 4; it++) {
            int i = tid + it * 256;
            int qq = i >> 7, mm = i & 127;
            p_s[qq * 132 + mm] = __expf(sr[it] - rowmax[qq]) * rowinv[qq];
        }
        #pragma unroll
        for (int it = 0; it < 8; it++) {
            int i = tid + it * 256;
            *(float4*)&v_s[(i >> 5) * 132 + ((i & 31) << 2)] = vr[it];
        }
        __syncthreads();

        if (c + 128 < NK)
            k3_load_chunk(scores, value, qbase, c + 128, tid, vr, sr);  // overlap

        #pragma unroll
        for (int mg = 0; mg < 64; mg += 4) {
            ulonglong2 p2 = *(const ulonglong2*)&p_s[q * 132 + mb + mg];
            #pragma unroll
            for (int j = 0; j < 4; j++) {
                ulonglong2 v2 = *(const ulonglong2*)&v_s[(dg * 4 + j) * 132 + mb + mg];
                fma2(acc2[j], p2.x, v2.x);
                fma2(acc2[j], p2.y, v2.y);
            }
        }
    }

    float accs[4];
    #pragma unroll
    for (int j = 0; j < 4; j++) {
        float2 f = upk(acc2[j]);
        accs[j] = f.x + f.y;
    }

    // cross m-half reduction (reuse v_s)
    __syncthreads();
    if (mh == 1)
        *(float4*)&v_s[(tid - 128) * 4] = make_float4(accs[0], accs[1], accs[2], accs[3]);
    __syncthreads();
    if (mh == 0) {
        float4 other = *(const float4*)&v_s[tid * 4];
        accs[0] += other.x; accs[1] += other.y;
        accs[2] += other.z; accs[3] += other.w;
        #pragma unroll
        for (int j = 0; j < 4; j++)
            out[(dg * 4 + j) * NQ + qbase + q] = accs[j];
    }
}

// ---------------------------------------------------------------------------
// Launch: out = d_out[0 : 64*1024], scores = d_out[64*1024 : +1024*2048]
// ---------------------------------------------------------------------------
extern "C" void kernel_launch(void* const* d_in, const int* in_sizes, int n_in,
                              void* d_out, int out_size)
{
    const float* query = (const float*)d_in[0];
    const float* key   = (const float*)d_in[1];
    const float* value = (const float*)d_in[2];
    const float* W1    = (const float*)d_in[3];
    const float* b1    = (const float*)d_in[4];
    const float* W2    = (const float*)d_in[5];
    const float* b2    = (const float*)d_in[6];

    float* out    = (float*)d_out;
    float* scores = out + D * NQ;

    k1_project<<<dim3((NQ + NK) / 32, 2), 256>>>(query, key, W1, b1);
    k2_scores<<<dim3(NK / 128, NQ / 64), 256>>>(W2, b2, scores);
    k3_softmax_pv<<<NQ / 8, 256>>>(scores, value, out);
}

// round 8
// speedup vs baseline: 2.8697x; 1.1072x over previous
#include <cuda_runtime.h>
#include <cuda_bf16.h>

// Problem constants (fixed by setup_inputs): d=64, nq=1024, nk=2048, batch=1
#define D   64
#define NQ  1024
#define NK  2048

typedef unsigned long long ull;

// Scratch: projected features stored TRANSPOSED (h-major)
__device__ float g_qpbT[D * NQ];   // qpbT[h][q] = b1[h] + sum_d W1q[h][d] query[d][q]
__device__ float g_kpbT[D * NK];   // kpbT[h][k] =         sum_d W1k[h][d] key[d][k]

// ---- packed f32x2 helpers -------------------------------------------------
__device__ __forceinline__ void fma2(ull& acc, ull a, ull b) {
    asm("fma.rn.f32x2 %0, %1, %2, %0;" : "+l"(acc) : "l"(a), "l"(b));
}
__device__ __forceinline__ void relu_wfma2(ull& acc, ull q2, ull k2, ull w2) {
    asm("{\n\t"
        ".reg .b64 t;\n\t"
        ".reg .f32 lo, hi;\n\t"
        "add.rn.f32x2 t, %1, %2;\n\t"
        "mov.b64 {lo, hi}, t;\n\t"
        "max.f32 lo, lo, 0f00000000;\n\t"
        "max.f32 hi, hi, 0f00000000;\n\t"
        "mov.b64 t, {lo, hi};\n\t"
        "fma.rn.f32x2 %0, %3, t, %0;\n\t"
        "}" : "+l"(acc) : "l"(q2), "l"(k2), "l"(w2));
}
__device__ __forceinline__ float2 upk(ull v) {
    float2 f;
    asm("mov.b64 {%0, %1}, %2;" : "=f"(f.x), "=f"(f.y) : "l"(v));
    return f;
}
__device__ __forceinline__ ull pk(float a, float b) {
    ull r;
    asm("mov.b64 %0, {%1, %2};" : "=l"(r) : "f"(a), "f"(b));
    return r;
}

// ---------------------------------------------------------------------------
// K1: projection GEMMs. Block = 32 cols x 16 h (h-split x4 -> grid (96,4)).
// 256 threads = 32 cols x 8 warps x 2 h each.
// ---------------------------------------------------------------------------
__global__ __launch_bounds__(256)
void k1_project(const float* __restrict__ query,
                const float* __restrict__ key,
                const float* __restrict__ W1,
                const float* __restrict__ b1)
{
    __shared__ float in_s[64 * 32];   // [d][c]
    __shared__ float w_s[64 * 20];    // [d][hl], pad 20

    int tid     = threadIdx.x;
    int colbase = blockIdx.x * 32;
    int hbase   = blockIdx.y * 16;
    bool isQ    = (colbase < NQ);
    int off     = isQ ? 0 : 64;
    int stride  = isQ ? NQ : NK;
    int cb      = isQ ? colbase : colbase - NQ;
    const float* src = isQ ? query : key;

    // input tile 64d x 32c, float4 coalesced (512 float4, 2 iters)
    #pragma unroll
    for (int it = 0; it < 2; it++) {
        int i = tid + it * 256;            // float4 index
        int d = i >> 3, c4 = (i & 7) << 2;
        *(float4*)&in_s[d * 32 + c4] = *(const float4*)&src[d * stride + cb + c4];
    }
    // weight tile: 16 h x 64 d, transposed into [d][hl]
    #pragma unroll
    for (int it = 0; it < 4; it++) {
        int i = tid + it * 256;
        int d = i & 63, hl = i >> 6;
        w_s[d * 20 + hl] = W1[(hbase + hl) * 128 + off + d];
    }
    __syncthreads();

    int lane = tid & 31;
    int hl0  = (tid >> 5) * 2;

    float acc0 = isQ ? b1[hbase + hl0]     : 0.0f;
    float acc1 = isQ ? b1[hbase + hl0 + 1] : 0.0f;

    #pragma unroll 16
    for (int d = 0; d < 64; d++) {
        float  x  = in_s[d * 32 + lane];
        float2 wv = *(const float2*)&w_s[d * 20 + hl0];
        acc0 = fmaf(wv.x, x, acc0);
        acc1 = fmaf(wv.y, x, acc1);
    }

    float* dst = isQ ? g_qpbT : g_kpbT;
    dst[(hbase + hl0)     * stride + cb + lane] = acc0;
    dst[(hbase + hl0 + 1) * stride + cb + lane] = acc1;
}

// ---------------------------------------------------------------------------
// K2: scores[q][k] = b2 + sum_h W2[h] * relu(qpb[q][h] + kpb[k][h])
// Tile 64q x 128k per block, 256 threads, per-thread 4q x 8k, packed f32x2.
// Grid (NK/128, NQ/64) = (16, 16).
// ---------------------------------------------------------------------------
__global__ __launch_bounds__(256)
void k2_scores(const float* __restrict__ W2,
               const float* __restrict__ b2,
               float* __restrict__ scores)
{
    __shared__ float qs2[64 * 132];   // [h][2*64]  duplicated q values
    __shared__ float ks [64 * 132];   // [h][128]
    __shared__ float w2d[128];        // duplicated W2

    int tid   = threadIdx.x;
    int qbase = blockIdx.y * 64;
    int kbase = blockIdx.x * 128;

    #pragma unroll
    for (int it = 0; it < 16; it++) {
        int i = tid + it * 256;               // 64h x 64r
        int h = i >> 6, r = i & 63;
        float v = g_qpbT[h * NQ + qbase + r];
        *(float2*)&qs2[h * 132 + 2 * r] = make_float2(v, v);
    }
    #pragma unroll
    for (int it = 0; it < 8; it++) {
        int i = tid + it * 256;               // 64h x 32 float4
        int h = i >> 5, c4 = (i & 31) << 2;
        *(float4*)&ks[h * 132 + c4] = *(const float4*)&g_kpbT[h * NK + kbase + c4];
    }
    if (tid < 64) {
        float w = W2[tid];
        *(float2*)&w2d[2 * tid] = make_float2(w, w);
    }
    __syncthreads();

    int qg = tid >> 4;        // 0..15 -> q rows 4qg..4qg+3
    int kg = tid & 15;        // 0..15 -> k cols {4kg..} u {64+4kg..}

    ull acc[4][4];
    #pragma unroll
    for (int i = 0; i < 4; i++)
        #pragma unroll
        for (int j = 0; j < 4; j++) acc[i][j] = 0ull;

    #pragma unroll 4
    for (int h = 0; h < 64; h++) {
        ull w2v = *(const ull*)&w2d[2 * h];
        const float* qrow = &qs2[h * 132 + 8 * qg];
        ulonglong2 qA = *(const ulonglong2*)qrow;
        ulonglong2 qB = *(const ulonglong2*)(qrow + 4);
        ulonglong2 kA = *(const ulonglong2*)&ks[h * 132 + 4 * kg];
        ulonglong2 kB = *(const ulonglong2*)&ks[h * 132 + 64 + 4 * kg];
        ull qd[4] = {qA.x, qA.y, qB.x, qB.y};
        ull kp[4] = {kA.x, kA.y, kB.x, kB.y};
        #pragma unroll
        for (int i = 0; i < 4; i++)
            #pragma unroll
            for (int j = 0; j < 4; j++)
                relu_wfma2(acc[i][j], qd[i], kp[j], w2v);
    }

    float bias = b2[0];
    #pragma unroll
    for (int i = 0; i < 4; i++) {
        float* row = &scores[(qbase + 4 * qg + i) * NK + kbase];
        float2 a0 = upk(acc[i][0]), a1 = upk(acc[i][1]);
        float2 a2 = upk(acc[i][2]), a3 = upk(acc[i][3]);
        *(float4*)&row[4 * kg] =
            make_float4(a0.x + bias, a0.y + bias, a1.x + bias, a1.y + bias);
        *(float4*)&row[64 + 4 * kg] =
            make_float4(a2.x + bias, a2.y + bias, a3.x + bias, a3.y + bias);
    }
}

// ---------------------------------------------------------------------------
// K3: softmax over k + out[d][q] = sum_m prob[q][m] * value[d][m]
// Block = 8 q rows x ALL 64 d, 256 threads, grid 128 (one wave).
// Thread (dg, ms): dg = tid>>4 owns d rows 4dg..4dg+3; ms = tid&15 owns the
// private m-slice [ms*8, ms*8+8) of every 128-m chunk (m-split 16, reduced in
// smem at the end). v is thread-private -> registers straight from gmem (NO v
// smem, NO v LDS). p in smem with XOR swizzle (kills the stride-32B conflict).
// ---------------------------------------------------------------------------
__global__ __launch_bounds__(256)
void k3_softmax_pv(const float* __restrict__ scores,
                   const float* __restrict__ value,
                   float* __restrict__ out)
{
    __shared__ float rowmax[8], rowinv[8];
    __shared__ float p_s[8 * 132];
    __shared__ float red[256 * 32];

    int tid   = threadIdx.x;
    int qbase = blockIdx.x * 8;
    int w     = tid >> 5;
    int lane  = tid & 31;

    // --- softmax stats: one warp per q row, 4 independent partials ---
    {
        const float* srow = scores + (qbase + w) * NK;
        float a = -1e30f, b = -1e30f, cc = -1e30f, d = -1e30f;
        #pragma unroll
        for (int i = 0; i < NK; i += 128) {
            a  = fmaxf(a,  srow[i + lane]);
            b  = fmaxf(b,  srow[i + lane + 32]);
            cc = fmaxf(cc, srow[i + lane + 64]);
            d  = fmaxf(d,  srow[i + lane + 96]);
        }
        float lm = fmaxf(fmaxf(a, b), fmaxf(cc, d));
        #pragma unroll
        for (int o = 16; o > 0; o >>= 1)
            lm = fmaxf(lm, __shfl_xor_sync(0xffffffffu, lm, o));

        float sa = 0.0f, sb = 0.0f, sc = 0.0f, sd = 0.0f;
        #pragma unroll
        for (int i = 0; i < NK; i += 128) {
            sa += __expf(srow[i + lane]      - lm);
            sb += __expf(srow[i + lane + 32] - lm);
            sc += __expf(srow[i + lane + 64] - lm);
            sd += __expf(srow[i + lane + 96] - lm);
        }
        float ls = (sa + sb) + (sc + sd);
        #pragma unroll
        for (int o = 16; o > 0; o >>= 1)
            ls += __shfl_xor_sync(0xffffffffu, ls, o);

        if (lane == 0) { rowmax[w] = lm; rowinv[w] = 1.0f / ls; }
    }

    int ms = tid & 15;          // m-slice owner
    int dg = tid >> 4;          // 4 d rows: 4dg..4dg+3
    int m0 = ms * 8;

    ull acc[4][8];              // [d_local][q], packed over m-pairs
    #pragma unroll
    for (int j = 0; j < 4; j++)
        #pragma unroll
        for (int q = 0; q < 8; q++) acc[j][q] = 0ull;

    // preload scores for chunk 0 (p staging operands)
    float sr[4];
    #pragma unroll
    for (int it = 0; it < 4; it++) {
        int i = tid + it * 256;
        sr[it] = scores[(qbase + (i >> 7)) * NK + (i & 127)];
    }

    for (int c = 0; c < NK; c += 128) {
        // v: thread-private 4d x 8m straight to registers
        float4 vr[8];
        #pragma unroll
        for (int j = 0; j < 4; j++) {
            const float* vrow = &value[(4 * dg + j) * NK + c + m0];
            vr[j * 2]     = *(const float4*)(vrow);
            vr[j * 2 + 1] = *(const float4*)(vrow + 4);
        }

        __syncthreads();
        // stage p (swizzled)
        #pragma unroll
        for (int it = 0; it < 4; it++) {
            int i  = tid + it * 256;
            int qq = i >> 7, mm = i & 127;
            int pm = mm ^ (((mm >> 3) & 7) << 2);
            p_s[qq * 132 + pm] = __expf(sr[it] - rowmax[qq]) * rowinv[qq];
        }
        __syncthreads();

        // prefetch next chunk's scores
        if (c + 128 < NK) {
            #pragma unroll
            for (int it = 0; it < 4; it++) {
                int i = tid + it * 256;
                sr[it] = scores[(qbase + (i >> 7)) * NK + c + 128 + (i & 127)];
            }
        }

        // compute: 2 quads x 8 q x 4 d, all packed over m
        #pragma unroll
        for (int quad = 0; quad < 2; quad++) {
            int mp = (m0 + quad * 4) ^ ((ms & 7) << 2);
            ull v01[4], v23[4];
            #pragma unroll
            for (int j = 0; j < 4; j++) {
                float4 v4 = vr[j * 2 + quad];
                v01[j] = pk(v4.x, v4.y);
                v23[j] = pk(v4.z, v4.w);
            }
            #pragma unroll
            for (int q = 0; q < 8; q++) {
                ulonglong2 p2 = *(const ulonglong2*)&p_s[q * 132 + mp];
                #pragma unroll
                for (int j = 0; j < 4; j++) {
                    fma2(acc[j][q], p2.x, v01[j]);
                    fma2(acc[j][q], p2.y, v23[j]);
                }
            }
        }
    }

    // --- epilogue: horizontal m-pair sum, then 16-way ms reduce in smem ---
    __syncthreads();
    #pragma unroll
    for (int j = 0; j < 4; j++) {
        float s[8];
        #pragma unroll
        for (int q = 0; q < 8; q++) {
            float2 f = upk(acc[j][q]);
            s[q] = f.x + f.y;
        }
        *(float4*)&red[tid * 32 + j * 8]     = make_float4(s[0], s[1], s[2], s[3]);
        *(float4*)&red[tid * 32 + j * 8 + 4] = make_float4(s[4], s[5], s[6], s[7]);
    }
    __syncthreads();

    #pragma unroll
    for (int r = 0; r < 2; r++) {
        int o   = tid + r * 256;      // 512 outputs: 64d x 8q
        int d   = o >> 3, q = o & 7;
        int dgr = d >> 2, dl = d & 3;
        float s0 = 0.0f, s1 = 0.0f, s2 = 0.0f, s3 = 0.0f;
        #pragma unroll
        for (int m = 0; m < 16; m += 4) {
            s0 += red[(dgr * 16 + m)     * 32 + dl * 8 + q];
            s1 += red[(dgr * 16 + m + 1) * 32 + dl * 8 + q];
            s2 += red[(dgr * 16 + m + 2) * 32 + dl * 8 + q];
            s3 += red[(dgr * 16 + m + 3) * 32 + dl * 8 + q];
        }
        out[d * NQ + qbase + q] = (s0 + s1) + (s2 + s3);
    }
}

// ---------------------------------------------------------------------------
// Launch: out = d_out[0 : 64*1024], scores = d_out[64*1024 : +1024*2048]
// ---------------------------------------------------------------------------
extern "C" void kernel_launch(void* const* d_in, const int* in_sizes, int n_in,
                              void* d_out, int out_size)
{
    const float* query = (const float*)d_in[0];
    const float* key   = (const float*)d_in[1];
    const float* value = (const float*)d_in[2];
    const float* W1    = (const float*)d_in[3];
    const float* b1    = (const float*)d_in[4];
    const float* W2    = (const float*)d_in[5];
    const float* b2    = (const float*)d_in[6];

    float* out    = (float*)d_out;
    float* scores = out + D * NQ;

    k1_project<<<dim3((NQ + NK) / 32, 4), 256>>>(query, key, W1, b1);
    k2_scores<<<dim3(NK / 128, NQ / 64), 256>>>(W2, b2, scores);
    k3_softmax_pv<<<NQ / 8, 256>>>(scores, value, out);
}